// round 4
// baseline (speedup 1.0000x reference)
#include <cuda_runtime.h>
#include <math.h>

#define HW 128
#define NPIX (HW*HW)
#define NF 512
#define NP 256
#define SIGMAINV 7000.0f
#define BBOX_M 0.06f
#define DLB_T 0.055f

// Per-face precomputed tables (AoS of float4, 4 per face each).
// hot:  [0]=bbox(xmin-m, xmax+m, ymin-m, ymax+m) (poisoned if !front||!valid)
//       [1]=(x0,y0,x1,y1)  [2]=(x2,y2,invden,0)  [3]=(h0,h1,h2,0)
// cold: [0]=(z0,z1,z2,0)   [1..3]=vertex colors (r,g,b,0)
__device__ float4 g_hot[NF * 4];
__device__ float4 g_cold[NF * 4];

__global__ __launch_bounds__(256)
void preproc_kernel(const float* __restrict__ pts,
                    const float* __restrict__ cols,
                    const float* __restrict__ rot,
                    const float* __restrict__ cpos,
                    const float* __restrict__ proj,
                    const int* __restrict__ faces,
                    float* __restrict__ out) {
    int f = blockIdx.x * blockDim.x + threadIdx.x;
    if (f >= NF) return;

    float r00 = rot[0], r01 = rot[1], r02 = rot[2];
    float r10 = rot[3], r11 = rot[4], r12 = rot[5];
    float r20 = rot[6], r21 = rot[7], r22 = rot[8];
    float cx = cpos[0], cy = cpos[1], cz = cpos[2];
    float pr0 = proj[0], pr1 = proj[1], pr2 = proj[2];

    int idx[3];
    idx[0] = faces[f * 3 + 0];
    idx[1] = faces[f * 3 + 1];
    idx[2] = faces[f * 3 + 2];

    float camx[3], camy[3], camz[3], sx[3], sy[3];
#pragma unroll
    for (int k = 0; k < 3; k++) {
        float qx = pts[idx[k] * 3 + 0] - cx;
        float qy = pts[idx[k] * 3 + 1] - cy;
        float qz = pts[idx[k] * 3 + 2] - cz;
        float X = qx * r00 + qy * r01 + qz * r02;
        float Y = qx * r10 + qy * r11 + qz * r12;
        float Z = qx * r20 + qy * r21 + qz * r22;
        camx[k] = X; camy[k] = Y; camz[k] = Z;
        sx[k] = (X * pr0) / (Z * pr2);
        sy[k] = (Y * pr1) / (Z * pr2);
    }

    // normal in camera space (matches reference cross(pf1-pf0, pf2-pf0))
    float e1x = camx[1] - camx[0], e1y = camy[1] - camy[0], e1z = camz[1] - camz[0];
    float e2x = camx[2] - camx[0], e2y = camy[2] - camy[0], e2z = camz[2] - camz[0];
    float nx = e1y * e2z - e1z * e2y;
    float ny = e1z * e2x - e1x * e2z;
    float nz = e1x * e2y - e1y * e2x;
    float nlen = sqrtf(nx * nx + ny * ny + nz * nz + 1e-8f);
    float ninv = 1.0f / (nlen + 1e-15f);
    out[NPIX * 4 + f * 3 + 0] = nx * ninv;
    out[NPIX * 4 + f * 3 + 1] = ny * ninv;
    out[NPIX * 4 + f * 3 + 2] = nz * ninv;

    float area = (sx[1] - sx[0]) * (sy[2] - sy[0]) - (sx[2] - sx[0]) * (sy[1] - sy[0]);
    bool ok = (nz > 0.0f) && (fabsf(area) > 1e-10f);

    float4 bb;
    if (ok) {
        bb.x = fminf(fminf(sx[0], sx[1]), sx[2]) - BBOX_M;
        bb.y = fmaxf(fmaxf(sx[0], sx[1]), sx[2]) + BBOX_M;
        bb.z = fminf(fminf(sy[0], sy[1]), sy[2]) - BBOX_M;
        bb.w = fmaxf(fmaxf(sy[0], sy[1]), sy[2]) + BBOX_M;
    } else {
        bb = make_float4(1e30f, -1e30f, 1e30f, -1e30f);  // always rejected
    }

    float aabs = fabsf(area);
    float L0 = sqrtf((sx[2] - sx[1]) * (sx[2] - sx[1]) + (sy[2] - sy[1]) * (sy[2] - sy[1]));
    float L1 = sqrtf((sx[0] - sx[2]) * (sx[0] - sx[2]) + (sy[0] - sy[2]) * (sy[0] - sy[2]));
    float L2 = sqrtf((sx[1] - sx[0]) * (sx[1] - sx[0]) + (sy[1] - sy[0]) * (sy[1] - sy[0]));
    float h0 = aabs / fmaxf(L0, 1e-20f);
    float h1 = aabs / fmaxf(L1, 1e-20f);
    float h2 = aabs / fmaxf(L2, 1e-20f);

    g_hot[f * 4 + 0] = bb;
    g_hot[f * 4 + 1] = make_float4(sx[0], sy[0], sx[1], sy[1]);
    g_hot[f * 4 + 2] = make_float4(sx[2], sy[2], ok ? (1.0f / area) : 0.0f, 0.0f);
    g_hot[f * 4 + 3] = make_float4(h0, h1, h2, 0.0f);

    g_cold[f * 4 + 0] = make_float4(camz[0], camz[1], camz[2], 0.0f);
    g_cold[f * 4 + 1] = make_float4(cols[idx[0] * 3 + 0], cols[idx[0] * 3 + 1], cols[idx[0] * 3 + 2], 0.0f);
    g_cold[f * 4 + 2] = make_float4(cols[idx[1] * 3 + 0], cols[idx[1] * 3 + 1], cols[idx[1] * 3 + 2], 0.0f);
    g_cold[f * 4 + 3] = make_float4(cols[idx[2] * 3 + 0], cols[idx[2] * 3 + 1], cols[idx[2] * 3 + 2], 0.0f);
}

__device__ __forceinline__ float seg_d2(float px, float py, float ax, float ay,
                                        float bx, float by) {
    float abx = bx - ax, aby = by - ay;
    float apx = px - ax, apy = py - ay;
    float t = (apx * abx + apy * aby) / (abx * abx + aby * aby + 1e-10f);
    t = fminf(fmaxf(t, 0.0f), 1.0f);
    float dx = apx - t * abx;
    float dy = apy - t * aby;
    return dx * dx + dy * dy;
}

// 8 pixels per warp, faces split x4 across lane groups (sub = lane>>3).
__global__ __launch_bounds__(128)
void raster_kernel(float* __restrict__ out) {
    int t = threadIdx.x;
    int lane = t & 31;
    int warp = t >> 5;
    int sub = lane >> 3;
    int pix = lane & 7;
    int p = blockIdx.x * 32 + warp * 8 + pix;
    int ix = p & (HW - 1);
    int iy = p >> 7;

    float px = (ix + 0.5f) * (2.0f / HW) - 1.0f;
    float py = 1.0f - (iy + 0.5f) * (2.0f / HW);

    int fbeg = sub * (NF / 4);
    int fend = fbeg + (NF / 4);

    float prodv = 1.0f;
    float zmin = 3.0e38f;
    float rr = 0.0f, gg = 0.0f, bc = 0.0f;

    for (int f = fbeg; f < fend; f++) {
        float4 bb = __ldg(&g_hot[f * 4 + 0]);
        if (px < bb.x || px > bb.y || py < bb.z || py > bb.w) continue;

        float4 v01 = __ldg(&g_hot[f * 4 + 1]);
        float4 v2i = __ldg(&g_hot[f * 4 + 2]);
        float w0 = ((v01.z - px) * (v2i.y - py) - (v2i.x - px) * (v01.w - py)) * v2i.z;
        float w1 = ((v2i.x - px) * (v01.y - py) - (v01.x - px) * (v2i.y - py)) * v2i.z;
        float w2 = 1.0f - w0 - w1;

        if (w0 >= 0.0f && w1 >= 0.0f && w2 >= 0.0f) {
            prodv = 0.0f;  // probf = exp(0) = 1 inside
            float4 zz = __ldg(&g_cold[f * 4 + 0]);
            float z = w0 * zz.x + w1 * zz.y + w2 * zz.z;
            if (z < zmin) {  // strict < keeps first occurrence (argmin semantics)
                zmin = z;
                float4 c0 = __ldg(&g_cold[f * 4 + 1]);
                float4 c1 = __ldg(&g_cold[f * 4 + 2]);
                float4 c2 = __ldg(&g_cold[f * 4 + 3]);
                rr = w0 * c0.x + w1 * c1.x + w2 * c2.x;
                gg = w0 * c0.y + w1 * c1.y + w2 * c2.y;
                bc = w0 * c0.z + w1 * c1.z + w2 * c2.z;
            }
        } else if (prodv != 0.0f) {
            float4 hh = __ldg(&g_hot[f * 4 + 3]);
            // lower bound on distance to triangle; if > DLB_T, (1-probf)==1.0f exactly
            float dlb = fmaxf(fmaxf(-w0 * hh.x, -w1 * hh.y), -w2 * hh.z);
            if (dlb < DLB_T) {
                float d2 = seg_d2(px, py, v01.x, v01.y, v01.z, v01.w);
                d2 = fminf(d2, seg_d2(px, py, v01.z, v01.w, v2i.x, v2i.y));
                d2 = fminf(d2, seg_d2(px, py, v2i.x, v2i.y, v01.x, v01.y));
                prodv *= (1.0f - expf(-d2 * SIGMAINV));
            }
        }
    }

    // Combine the 4 face-range partials (butterfly over sub groups).
    const unsigned m = 0xFFFFFFFFu;
    float z = zmin;
    int q = sub;
#pragma unroll
    for (int off = 8; off <= 16; off <<= 1) {
        float oz = __shfl_xor_sync(m, z, off);
        int oq = __shfl_xor_sync(m, q, off);
        float orr = __shfl_xor_sync(m, rr, off);
        float ogg = __shfl_xor_sync(m, gg, off);
        float obc = __shfl_xor_sync(m, bc, off);
        float op = __shfl_xor_sync(m, prodv, off);
        prodv *= op;
        bool take = (oz < z) || (oz == z && oq < q);  // lower face range wins ties
        if (take) { z = oz; q = oq; rr = orr; gg = ogg; bc = obc; }
    }

    if (sub == 0) {
        out[p * 3 + 0] = rr;
        out[p * 3 + 1] = gg;
        out[p * 3 + 2] = bc;
        out[NPIX * 3 + p] = 1.0f - prodv;
    }
}

extern "C" void kernel_launch(void* const* d_in, const int* in_sizes, int n_in,
                              void* d_out, int out_size) {
    const float* pts  = (const float*)d_in[0];
    const float* cols = (const float*)d_in[1];
    const float* rot  = (const float*)d_in[2];
    const float* cpos = (const float*)d_in[3];
    const float* proj = (const float*)d_in[4];
    const int*   fcs  = (const int*)d_in[5];
    float* out = (float*)d_out;

    preproc_kernel<<<2, 256>>>(pts, cols, rot, cpos, proj, fcs, out);
    raster_kernel<<<NPIX / 32, 128>>>(out);
}